// round 14
// baseline (speedup 1.0000x reference)
#include <cuda_runtime.h>
#include <stdint.h>

// ============================================================================
// ModeloNeuralVasicek — neural Vasicek SDE MC, exact-JAX-RNG, mean-collapsed,
// Taylor-windowed MLP with single-warp fast path.
// B=64, T=256, Q=256, n_steps=2520, d_h=128.
//
// pre_j(s) = A_j + B_j*(mean_r - mean_r_ref) + C_j*(s - s_ref)
//   A = b2 + W2·gelu(v_ref), B = W2·(g'·w1a), C = W2·(g'·w1b*F_TSTEP)
// Refresh every 16 steps by all 8 warps (exact MLP + gradients, reg-resident
// W2).  Between refreshes warp 0 alone advances the scalar recurrence:
// 8 units/lane, no barriers, no smem round trips; two s32 redux per step.
// ============================================================================

#define NSTEPS 2520
#define BB 64
#define TT 256
#define WIN 16
#define F_DT 0.003968253968253968f
#define F_SQRT_DT 0.06299407883487119f
#define F_TSTEP (1.0f / 2519.0f)
#define FIX_SCALE 2097152.0f          // 2^21
#define FIX_INV   (1.0f / 2097152.0f)

__device__ float g_H[BB * TT * 64];
__device__ float g_base[2][BB][128];
__device__ float g_zbar[BB * NSTEPS];
__device__ unsigned int g_keys[NSTEPS * 2];

// ---------------------------------------------------------------------------
__device__ __forceinline__ void threefry2x32(uint32_t k0, uint32_t k1,
                                             uint32_t x0, uint32_t x1,
                                             uint32_t& o0, uint32_t& o1) {
    uint32_t ks2 = k0 ^ k1 ^ 0x1BD11BDAu;
    x0 += k0; x1 += k1;
#define TFR(r) { x0 += x1; x1 = __funnelshift_l(x1, x1, (r)); x1 ^= x0; }
    TFR(13) TFR(15) TFR(26) TFR(6)
    x0 += k1; x1 += ks2 + 1u;
    TFR(17) TFR(29) TFR(16) TFR(24)
    x0 += ks2; x1 += k0 + 2u;
    TFR(13) TFR(15) TFR(26) TFR(6)
    x0 += k0; x1 += k1 + 3u;
    TFR(17) TFR(29) TFR(16) TFR(24)
    x0 += k1; x1 += ks2 + 4u;
    TFR(13) TFR(15) TFR(26) TFR(6)
    x0 += ks2; x1 += k0 + 5u;
#undef TFR
    o0 = x0; o1 = x1;
}

__device__ __forceinline__ float erfinv_xla(float x) {
    float w = -log1pf(-x * x);
    float p;
    if (w < 5.0f) {
        w = w - 2.5f;
        p = 2.81022636e-08f;
        p = fmaf(p, w, 3.43273939e-07f);
        p = fmaf(p, w, -3.5233877e-06f);
        p = fmaf(p, w, -4.39150654e-06f);
        p = fmaf(p, w, 0.00021858087f);
        p = fmaf(p, w, -0.00125372503f);
        p = fmaf(p, w, -0.00417768164f);
        p = fmaf(p, w, 0.246640727f);
        p = fmaf(p, w, 1.50140941f);
    } else {
        w = sqrtf(w) - 3.0f;
        p = -0.000200214257f;
        p = fmaf(p, w, 0.000100950558f);
        p = fmaf(p, w, 0.00134934322f);
        p = fmaf(p, w, -0.00367342844f);
        p = fmaf(p, w, 0.00573950773f);
        p = fmaf(p, w, -0.0076224613f);
        p = fmaf(p, w, 0.00943887047f);
        p = fmaf(p, w, 1.00167406f);
        p = fmaf(p, w, 2.83297682f);
    }
    return p * x;
}

__device__ __forceinline__ float gelu_exact(float x) {
    return 0.5f * x * (1.0f + erff(x * 0.70710678118654752f));
}

__device__ __forceinline__ void gelu_vd(float x, float& g, float& gp) {
    float e = erff(x * 0.70710678118654752f);
    float Phi = fmaf(0.5f, e, 0.5f);
    g = x * Phi;
    float phi = 0.3989422804014327f * __expf(-0.5f * x * x);
    gp = fmaf(x, phi, Phi);
}

__device__ __forceinline__ unsigned long long fma2(unsigned long long a,
                                                   unsigned long long b,
                                                   unsigned long long c) {
    unsigned long long d;
    asm("fma.rn.f32x2 %0, %1, %2, %3;" : "=l"(d) : "l"(a), "l"(b), "l"(c));
    return d;
}
__device__ __forceinline__ unsigned long long pack2(float lo, float hi) {
    unsigned long long v;
    asm("mov.b64 %0, {%1, %2};" : "=l"(v) : "f"(lo), "f"(hi));
    return v;
}
__device__ __forceinline__ float2 unpack2(unsigned long long v) {
    float2 r;
    asm("mov.b64 {%0, %1}, %2;" : "=f"(r.x), "=f"(r.y) : "l"(v));
    return r;
}

__device__ __forceinline__ float wredsum(float v) {
#pragma unroll
    for (int o = 16; o > 0; o >>= 1) v += __shfl_xor_sync(0xFFFFFFFFu, v, o);
    return v;
}

__device__ __forceinline__ int redux_add_s32(int v) {
    int r;
    asm("redux.sync.add.s32 %0, %1, 0xffffffff;" : "=r"(r) : "r"(v));
    return r;
}

__device__ __forceinline__ float dot128(const ulonglong2* hp,
                                        const unsigned long long* w2) {
    unsigned long long a0 = 0ull, a1 = 0ull, a2 = 0ull, a3 = 0ull;
    unsigned long long a4 = 0ull, a5 = 0ull, a6 = 0ull, a7 = 0ull;
#pragma unroll
    for (int i = 0; i < 8; i++) {
        ulonglong2 h01 = hp[4 * i + 0];
        ulonglong2 h23 = hp[4 * i + 1];
        ulonglong2 h45 = hp[4 * i + 2];
        ulonglong2 h67 = hp[4 * i + 3];
        a0 = fma2(h01.x, w2[8 * i + 0], a0);
        a1 = fma2(h01.y, w2[8 * i + 1], a1);
        a2 = fma2(h23.x, w2[8 * i + 2], a2);
        a3 = fma2(h23.y, w2[8 * i + 3], a3);
        a4 = fma2(h45.x, w2[8 * i + 4], a4);
        a5 = fma2(h45.y, w2[8 * i + 5], a5);
        a6 = fma2(h67.x, w2[8 * i + 6], a6);
        a7 = fma2(h67.y, w2[8 * i + 7], a7);
    }
    const unsigned long long one2 = 0x3F8000003F800000ull;
    a0 = fma2(a1, one2, a0);
    a2 = fma2(a3, one2, a2);
    a4 = fma2(a5, one2, a4);
    a6 = fma2(a7, one2, a6);
    float2 f0 = unpack2(a0), f2 = unpack2(a2), f4 = unpack2(a4), f6 = unpack2(a6);
    return ((f0.x + f0.y) + (f2.x + f2.y)) + ((f4.x + f4.y) + (f6.x + f6.y));
}

// ---------------------------------------------------------------------------
__global__ void keys_kernel() {
    int j = blockIdx.x * blockDim.x + threadIdx.x;
    if (j >= NSTEPS) return;
    uint32_t o0, o1;
    threefry2x32(0u, 1u, 0u, (uint32_t)j, o0, o1);
    g_keys[2 * j]     = o0;
    g_keys[2 * j + 1] = o1;
}

__global__ void zbar_kernel() {
    __shared__ float part[8];
    const int s = blockIdx.x, b = blockIdx.y, tid = threadIdx.x;
    const int warp = tid >> 5, lane = tid & 31;

    uint32_t k0 = __ldg(&g_keys[2 * s]);
    uint32_t k1 = __ldg(&g_keys[2 * s + 1]);
    uint32_t o0, o1;
    threefry2x32(k0, k1, 0u, (uint32_t)(b * 256 + tid), o0, o1);
    uint32_t bits = o0 ^ o1;

    float f = __uint_as_float((bits >> 9) | 0x3F800000u) - 1.0f;
    float u = fmaxf(fmaf(f, 2.0f, -0.99999994f), -0.99999994f);
    float z = 1.41421356237f * erfinv_xla(u);
    float dw = z * F_SQRT_DT;

    float sum = wredsum(dw);
    if (lane == 0) part[warp] = sum;
    __syncthreads();
    if (tid == 0) {
        float t = (((part[0] + part[1]) + (part[2] + part[3])) +
                   ((part[4] + part[5]) + (part[6] + part[7])));
        g_zbar[b * NSTEPS + s] = t * (1.0f / 256.0f);
    }
}

__global__ void prep_ctx_kernel(const float* __restrict__ X,
                                const float* __restrict__ Wp,
                                const float* __restrict__ bp,
                                const float* __restrict__ ln_g,
                                const float* __restrict__ ln_b,
                                const float* __restrict__ mu_W1,
                                const float* __restrict__ mu_b1,
                                const float* __restrict__ si_W1,
                                const float* __restrict__ si_b1) {
    __shared__ float ctx[192];
    const int b = blockIdx.x, tid = threadIdx.x;

    {
        const int t = tid;
        float x0 = X[(b * TT + t) * 2 + 0];
        float x1 = X[(b * TT + t) * 2 + 1];
        float h[64];
        float s = 0.0f;
#pragma unroll
        for (int j = 0; j < 64; j++) {
            float v = fmaf(x1, Wp[64 + j], fmaf(x0, Wp[j], bp[j]));
            h[j] = tanhf(v);
            s += h[j];
        }
        float m = s * (1.0f / 64.0f);
        float vv = 0.0f;
#pragma unroll
        for (int j = 0; j < 64; j++) { float d = h[j] - m; vv = fmaf(d, d, vv); }
        vv *= (1.0f / 64.0f);
        float den = sqrtf(vv + 1e-5f);
#pragma unroll
        for (int j = 0; j < 64; j++) {
            g_H[(b * TT + t) * 64 + j] = (h[j] - m) / den * ln_g[j] + ln_b[j];
        }
    }
    __syncthreads();

    if (tid < 64) {
        int j = tid;
        const float* Hb = g_H + b * TT * 64;
        float s = 0.0f;
        for (int t = 0; t < TT; t++) s += Hb[t * 64 + j];
        float mean = s * (1.0f / 256.0f);
        float ss = 0.0f;
        for (int t = 0; t < TT; t++) { float d = Hb[t * 64 + j] - mean; ss = fmaf(d, d, ss); }
        float sd = sqrtf(ss * (1.0f / 255.0f));
        ctx[j]       = mean;
        ctx[64 + j]  = sd;
        ctx[128 + j] = Hb[255 * 64 + j];
    }
    __syncthreads();
    int net = tid >> 7, j = tid & 127;
    const float* W1 = net ? si_W1 : mu_W1;
    float acc = (net ? si_b1 : mu_b1)[j];
    for (int i = 0; i < 192; i++)
        acc = fmaf(ctx[i], W1[(2 + i) * 128 + j], acc);
    g_base[net][b][j] = acc;
}

// ---------------------------------------------------------------------------
// SDE kernel: refresh (all warps) every WIN steps; warp 0 solo fast steps.
// ---------------------------------------------------------------------------
__global__ void __launch_bounds__(256, 1) sde_kernel(
    const float* __restrict__ r_ultimo, const float* __restrict__ mat,
    const float* __restrict__ mu_W1, const float* __restrict__ mu_W2,
    const float* __restrict__ mu_b2, const float* __restrict__ mu_W3,
    const float* __restrict__ mu_b3,
    const float* __restrict__ si_W1, const float* __restrict__ si_W2,
    const float* __restrict__ si_b2, const float* __restrict__ si_W3,
    const float* __restrict__ si_b3,
    float* __restrict__ out) {

    __shared__ __align__(16) float hg[2][128];
    __shared__ __align__(16) float hd1[2][128];
    __shared__ __align__(16) float hd2[2][128];
    __shared__ __align__(16) float As[256], Bs[256], Cs[256], W3v[256];
    __shared__ float sc_mean_r;
    __shared__ float zb[NSTEPS];

    const int b = blockIdx.x, tid = threadIdx.x;
    const int warp = tid >> 5, lane = tid & 31;

    for (int i = tid; i < NSTEPS; i += 256) zb[i] = g_zbar[b * NSTEPS + i];

    const int net = tid >> 7, j = tid & 127;
    const float* W1 = net ? si_W1 : mu_W1;
    const float* W2 = net ? si_W2 : mu_W2;
    const float w1a  = W1[j];
    const float w1b  = W1[128 + j];
    const float base = g_base[net][b][j];
    const float b2j  = (net ? si_b2 : mu_b2)[j];
    const float b3m  = mu_b3[0], b3s = si_b3[0];
    const float du   = w1b * F_TSTEP;

    W3v[tid] = (net ? si_W3 : mu_W3)[j] * FIX_SCALE;   // pre-scaled
    if (tid == 0) sc_mean_r = r_ultimo[b];

    unsigned long long w2[64];
#pragma unroll
    for (int i = 0; i < 64; i++)
        w2[i] = pack2(W2[(2 * i) * 128 + j], W2[(2 * i + 1) * 128 + j]);

    __syncthreads();                          // zb, W3v, sc_mean_r ready

    float asum = 0.0f;                        // meaningful in warp 0
    int s = 0;

    while (true) {
        // ---- refresh at step s (all warps, exact MLP + gradients) ----
        float mr = sc_mean_r;
        float tt = (float)s * F_TSTEP;
        float v = fmaf(w1b, tt, fmaf(w1a, mr, base));
        float g, gp;
        gelu_vd(v, g, gp);
        hg[net][j]  = g;
        hd1[net][j] = gp * w1a;
        hd2[net][j] = gp * du;
        __syncthreads();                      // (1) hg/hd ready
        float A = b2j + dot128((const ulonglong2*)(hg[net]),  w2);
        float B = dot128((const ulonglong2*)(hd1[net]), w2);
        float C = dot128((const ulonglong2*)(hd2[net]), w2);
        As[tid] = A; Bs[tid] = B; Cs[tid] = C;
        __syncthreads();                      // (2) As/Bs/Cs ready

        int e = s + WIN; if (e > NSTEPS) e = NSTEPS;

        if (warp == 0) {
            // per-lane coefficient slices: units 8*lane .. 8*lane+7
            const float4 A0 = *(const float4*)&As[lane * 8];
            const float4 A1 = *(const float4*)&As[lane * 8 + 4];
            const float4 B0 = *(const float4*)&Bs[lane * 8];
            const float4 B1 = *(const float4*)&Bs[lane * 8 + 4];
            const float4 C0 = *(const float4*)&Cs[lane * 8];
            const float4 C1 = *(const float4*)&Cs[lane * 8 + 4];
            const float4 W0 = *(const float4*)&W3v[lane * 8];
            const float4 W1v = *(const float4*)&W3v[lane * 8 + 4];
            const bool is_mu = (lane < 16);

            float mean_r = mr;
            float Dmr = 0.0f, fds = 0.0f;

            for (int ss = s; ss < e; ss++) {
                float zbs = zb[ss];
                float p0 = fmaf(B0.x, Dmr, fmaf(C0.x, fds, A0.x));
                float p1 = fmaf(B0.y, Dmr, fmaf(C0.y, fds, A0.y));
                float p2 = fmaf(B0.z, Dmr, fmaf(C0.z, fds, A0.z));
                float p3 = fmaf(B0.w, Dmr, fmaf(C0.w, fds, A0.w));
                float p4 = fmaf(B1.x, Dmr, fmaf(C1.x, fds, A1.x));
                float p5 = fmaf(B1.y, Dmr, fmaf(C1.y, fds, A1.y));
                float p6 = fmaf(B1.z, Dmr, fmaf(C1.z, fds, A1.z));
                float p7 = fmaf(B1.w, Dmr, fmaf(C1.w, fds, A1.w));
                float q0 = gelu_exact(p0) * W0.x;
                float q1 = gelu_exact(p1) * W0.y;
                float q2 = gelu_exact(p2) * W0.z;
                float q3 = gelu_exact(p3) * W0.w;
                float q4 = gelu_exact(p4) * W1v.x;
                float q5 = gelu_exact(p5) * W1v.y;
                float q6 = gelu_exact(p6) * W1v.z;
                float q7 = gelu_exact(p7) * W1v.w;
                float acc = ((q0 + q1) + (q2 + q3)) + ((q4 + q5) + (q6 + q7));
                int ia = __float2int_rn(acc);
                int Imu = is_mu ? ia : 0;
                int Isi = is_mu ? 0 : ia;
                int smu = redux_add_s32(Imu);
                int ssi = redux_add_s32(Isi);
                float mu = (float)smu * FIX_INV + b3m;
                float sp = (float)ssi * FIX_INV + b3s;
                float si = fmaxf(sp, 0.0f) +
                           __logf(1.0f + __expf(-fabsf(sp))) + 1e-5f;
                float dmr = fmaf(si, zbs, mu * F_DT);
                mean_r += dmr;
                Dmr += dmr;
                fds += 1.0f;
                asum = fmaf(mean_r, F_DT, asum);
            }
            if (lane == 0) sc_mean_r = mean_r;
        }
        s = e;
        __syncthreads();                      // (3) scalars published
        if (s >= NSTEPS) break;
    }

    if (tid < 7) {                            // warp 0 holds asum
        float maxT = 0.0f;
#pragma unroll
        for (int m = 0; m < 7; m++) maxT = fmaxf(maxT, mat[m]);
        float frac = mat[tid] / (maxT + 1e-12f);
        out[b * 7 + tid] = (asum * frac) / (mat[tid] + 1e-12f);
    }
}

// ---------------------------------------------------------------------------
extern "C" void kernel_launch(void* const* d_in, const int* in_sizes, int n_in,
                              void* d_out, int out_size) {
    const float* X        = (const float*)d_in[0];
    const float* r_ultimo = (const float*)d_in[1];
    const float* mat      = (const float*)d_in[2];
    const float* Wp       = (const float*)d_in[3];
    const float* bp       = (const float*)d_in[4];
    const float* ln_g     = (const float*)d_in[5];
    const float* ln_b     = (const float*)d_in[6];
    const float* mu_W1    = (const float*)d_in[7];
    const float* mu_b1    = (const float*)d_in[8];
    const float* mu_W2    = (const float*)d_in[9];
    const float* mu_b2    = (const float*)d_in[10];
    const float* mu_W3    = (const float*)d_in[11];
    const float* mu_b3    = (const float*)d_in[12];
    const float* si_W1    = (const float*)d_in[13];
    const float* si_b1    = (const float*)d_in[14];
    const float* si_W2    = (const float*)d_in[15];
    const float* si_b2    = (const float*)d_in[16];
    const float* si_W3    = (const float*)d_in[17];
    const float* si_b3    = (const float*)d_in[18];
    float* out = (float*)d_out;

    keys_kernel<<<(NSTEPS + 255) / 256, 256>>>();
    dim3 zgrid(NSTEPS, BB);
    zbar_kernel<<<zgrid, 256>>>();
    prep_ctx_kernel<<<BB, TT>>>(X, Wp, bp, ln_g, ln_b,
                                mu_W1, mu_b1, si_W1, si_b1);
    sde_kernel<<<BB, 256>>>(r_ultimo, mat,
                            mu_W1, mu_W2, mu_b2, mu_W3, mu_b3,
                            si_W1, si_W2, si_b2, si_W3, si_b3,
                            out);
}

// round 15
// speedup vs baseline: 1.8367x; 1.8367x over previous
#include <cuda_runtime.h>
#include <stdint.h>

// ============================================================================
// ModeloNeuralVasicek — neural Vasicek SDE MC, exact-JAX-RNG, mean-collapsed,
// fully scalar-linearized step map.  B=64, T=256, Q=256, n_steps=2520.
//
// Window refresh (every WIN steps, exact): per-unit pre-coefficients
//   A = b2 + W2·gelu(v), B = W2·(g1'·w1a), C = W2·(g1'·w1b·F_TSTEP)
// then outer linearization at pre=A:
//   mu(D,ds) ~ mu0 + muB*D + muC*ds,  sp(D,ds) ~ sp0 + spB*D + spC*ds
//   mu0 = w3'gelu(A)+b3, muB = w3'(g2'·B), muC = w3'(g2'·C)  (same for sp)
// Between refreshes ALL threads redundantly run the pure-scalar recurrence:
//   si = softplus(sp)+1e-5;  dmr = mu*DT + si*zbar[s];  D += dmr
// ~80-cycle chain, no barriers, no reductions, no gelu.
// ============================================================================

#define NSTEPS 2520
#define BB 64
#define TT 256
#define WIN 16
#define F_DT 0.003968253968253968f
#define F_SQRT_DT 0.06299407883487119f
#define F_TSTEP (1.0f / 2519.0f)

__device__ float g_H[BB * TT * 64];
__device__ float g_base[2][BB][128];
__device__ float g_zbar[BB * NSTEPS];
__device__ unsigned int g_keys[NSTEPS * 2];

// ---------------------------------------------------------------------------
__device__ __forceinline__ void threefry2x32(uint32_t k0, uint32_t k1,
                                             uint32_t x0, uint32_t x1,
                                             uint32_t& o0, uint32_t& o1) {
    uint32_t ks2 = k0 ^ k1 ^ 0x1BD11BDAu;
    x0 += k0; x1 += k1;
#define TFR(r) { x0 += x1; x1 = __funnelshift_l(x1, x1, (r)); x1 ^= x0; }
    TFR(13) TFR(15) TFR(26) TFR(6)
    x0 += k1; x1 += ks2 + 1u;
    TFR(17) TFR(29) TFR(16) TFR(24)
    x0 += ks2; x1 += k0 + 2u;
    TFR(13) TFR(15) TFR(26) TFR(6)
    x0 += k0; x1 += k1 + 3u;
    TFR(17) TFR(29) TFR(16) TFR(24)
    x0 += k1; x1 += ks2 + 4u;
    TFR(13) TFR(15) TFR(26) TFR(6)
    x0 += ks2; x1 += k0 + 5u;
#undef TFR
    o0 = x0; o1 = x1;
}

__device__ __forceinline__ float erfinv_xla(float x) {
    float w = -log1pf(-x * x);
    float p;
    if (w < 5.0f) {
        w = w - 2.5f;
        p = 2.81022636e-08f;
        p = fmaf(p, w, 3.43273939e-07f);
        p = fmaf(p, w, -3.5233877e-06f);
        p = fmaf(p, w, -4.39150654e-06f);
        p = fmaf(p, w, 0.00021858087f);
        p = fmaf(p, w, -0.00125372503f);
        p = fmaf(p, w, -0.00417768164f);
        p = fmaf(p, w, 0.246640727f);
        p = fmaf(p, w, 1.50140941f);
    } else {
        w = sqrtf(w) - 3.0f;
        p = -0.000200214257f;
        p = fmaf(p, w, 0.000100950558f);
        p = fmaf(p, w, 0.00134934322f);
        p = fmaf(p, w, -0.00367342844f);
        p = fmaf(p, w, 0.00573950773f);
        p = fmaf(p, w, -0.0076224613f);
        p = fmaf(p, w, 0.00943887047f);
        p = fmaf(p, w, 1.00167406f);
        p = fmaf(p, w, 2.83297682f);
    }
    return p * x;
}

__device__ __forceinline__ void gelu_vd(float x, float& g, float& gp) {
    float e = erff(x * 0.70710678118654752f);
    float Phi = fmaf(0.5f, e, 0.5f);
    g = x * Phi;
    float phi = 0.3989422804014327f * __expf(-0.5f * x * x);
    gp = fmaf(x, phi, Phi);
}

__device__ __forceinline__ unsigned long long fma2(unsigned long long a,
                                                   unsigned long long b,
                                                   unsigned long long c) {
    unsigned long long d;
    asm("fma.rn.f32x2 %0, %1, %2, %3;" : "=l"(d) : "l"(a), "l"(b), "l"(c));
    return d;
}
__device__ __forceinline__ unsigned long long pack2(float lo, float hi) {
    unsigned long long v;
    asm("mov.b64 %0, {%1, %2};" : "=l"(v) : "f"(lo), "f"(hi));
    return v;
}
__device__ __forceinline__ float2 unpack2(unsigned long long v) {
    float2 r;
    asm("mov.b64 {%0, %1}, %2;" : "=f"(r.x), "=f"(r.y) : "l"(v));
    return r;
}

__device__ __forceinline__ float wredsum(float v) {
#pragma unroll
    for (int o = 16; o > 0; o >>= 1) v += __shfl_xor_sync(0xFFFFFFFFu, v, o);
    return v;
}

__device__ __forceinline__ float dot128(const float* hpf,
                                        const unsigned long long* w2) {
    const ulonglong2* hp = (const ulonglong2*)hpf;
    unsigned long long a0 = 0ull, a1 = 0ull, a2 = 0ull, a3 = 0ull;
    unsigned long long a4 = 0ull, a5 = 0ull, a6 = 0ull, a7 = 0ull;
#pragma unroll
    for (int i = 0; i < 8; i++) {
        ulonglong2 h01 = hp[4 * i + 0];
        ulonglong2 h23 = hp[4 * i + 1];
        ulonglong2 h45 = hp[4 * i + 2];
        ulonglong2 h67 = hp[4 * i + 3];
        a0 = fma2(h01.x, w2[8 * i + 0], a0);
        a1 = fma2(h01.y, w2[8 * i + 1], a1);
        a2 = fma2(h23.x, w2[8 * i + 2], a2);
        a3 = fma2(h23.y, w2[8 * i + 3], a3);
        a4 = fma2(h45.x, w2[8 * i + 4], a4);
        a5 = fma2(h45.y, w2[8 * i + 5], a5);
        a6 = fma2(h67.x, w2[8 * i + 6], a6);
        a7 = fma2(h67.y, w2[8 * i + 7], a7);
    }
    const unsigned long long one2 = 0x3F8000003F800000ull;
    a0 = fma2(a1, one2, a0);
    a2 = fma2(a3, one2, a2);
    a4 = fma2(a5, one2, a4);
    a6 = fma2(a7, one2, a6);
    float2 f0 = unpack2(a0), f2 = unpack2(a2), f4 = unpack2(a4), f6 = unpack2(a6);
    return ((f0.x + f0.y) + (f2.x + f2.y)) + ((f4.x + f4.y) + (f6.x + f6.y));
}

// ---------------------------------------------------------------------------
__global__ void keys_kernel() {
    int j = blockIdx.x * blockDim.x + threadIdx.x;
    if (j >= NSTEPS) return;
    uint32_t o0, o1;
    threefry2x32(0u, 1u, 0u, (uint32_t)j, o0, o1);
    g_keys[2 * j]     = o0;
    g_keys[2 * j + 1] = o1;
}

__global__ void zbar_kernel() {
    __shared__ float part[8];
    const int s = blockIdx.x, b = blockIdx.y, tid = threadIdx.x;
    const int warp = tid >> 5, lane = tid & 31;

    uint32_t k0 = __ldg(&g_keys[2 * s]);
    uint32_t k1 = __ldg(&g_keys[2 * s + 1]);
    uint32_t o0, o1;
    threefry2x32(k0, k1, 0u, (uint32_t)(b * 256 + tid), o0, o1);
    uint32_t bits = o0 ^ o1;

    float f = __uint_as_float((bits >> 9) | 0x3F800000u) - 1.0f;
    float u = fmaxf(fmaf(f, 2.0f, -0.99999994f), -0.99999994f);
    float z = 1.41421356237f * erfinv_xla(u);
    float dw = z * F_SQRT_DT;

    float sum = wredsum(dw);
    if (lane == 0) part[warp] = sum;
    __syncthreads();
    if (tid == 0) {
        float t = (((part[0] + part[1]) + (part[2] + part[3])) +
                   ((part[4] + part[5]) + (part[6] + part[7])));
        g_zbar[b * NSTEPS + s] = t * (1.0f / 256.0f);
    }
}

__global__ void prep_ctx_kernel(const float* __restrict__ X,
                                const float* __restrict__ Wp,
                                const float* __restrict__ bp,
                                const float* __restrict__ ln_g,
                                const float* __restrict__ ln_b,
                                const float* __restrict__ mu_W1,
                                const float* __restrict__ mu_b1,
                                const float* __restrict__ si_W1,
                                const float* __restrict__ si_b1) {
    __shared__ float ctx[192];
    const int b = blockIdx.x, tid = threadIdx.x;

    {
        const int t = tid;
        float x0 = X[(b * TT + t) * 2 + 0];
        float x1 = X[(b * TT + t) * 2 + 1];
        float h[64];
        float s = 0.0f;
#pragma unroll
        for (int j = 0; j < 64; j++) {
            float v = fmaf(x1, Wp[64 + j], fmaf(x0, Wp[j], bp[j]));
            h[j] = tanhf(v);
            s += h[j];
        }
        float m = s * (1.0f / 64.0f);
        float vv = 0.0f;
#pragma unroll
        for (int j = 0; j < 64; j++) { float d = h[j] - m; vv = fmaf(d, d, vv); }
        vv *= (1.0f / 64.0f);
        float den = sqrtf(vv + 1e-5f);
#pragma unroll
        for (int j = 0; j < 64; j++) {
            g_H[(b * TT + t) * 64 + j] = (h[j] - m) / den * ln_g[j] + ln_b[j];
        }
    }
    __syncthreads();

    if (tid < 64) {
        int j = tid;
        const float* Hb = g_H + b * TT * 64;
        float s = 0.0f;
        for (int t = 0; t < TT; t++) s += Hb[t * 64 + j];
        float mean = s * (1.0f / 256.0f);
        float ss = 0.0f;
        for (int t = 0; t < TT; t++) { float d = Hb[t * 64 + j] - mean; ss = fmaf(d, d, ss); }
        float sd = sqrtf(ss * (1.0f / 255.0f));
        ctx[j]       = mean;
        ctx[64 + j]  = sd;
        ctx[128 + j] = Hb[255 * 64 + j];
    }
    __syncthreads();
    int net = tid >> 7, j = tid & 127;
    const float* W1 = net ? si_W1 : mu_W1;
    float acc = (net ? si_b1 : mu_b1)[j];
    for (int i = 0; i < 192; i++)
        acc = fmaf(ctx[i], W1[(2 + i) * 128 + j], acc);
    g_base[net][b][j] = acc;
}

// ---------------------------------------------------------------------------
// SDE kernel: exact refresh every WIN steps; in-window pure-scalar recurrence
// executed redundantly by all threads (no barriers, no reductions in-window).
// ---------------------------------------------------------------------------
__global__ void __launch_bounds__(256, 1) sde_kernel(
    const float* __restrict__ r_ultimo, const float* __restrict__ mat,
    const float* __restrict__ mu_W1, const float* __restrict__ mu_W2,
    const float* __restrict__ mu_b2, const float* __restrict__ mu_W3,
    const float* __restrict__ mu_b3,
    const float* __restrict__ si_W1, const float* __restrict__ si_W2,
    const float* __restrict__ si_b2, const float* __restrict__ si_W3,
    const float* __restrict__ si_b3,
    float* __restrict__ out) {

    __shared__ __align__(16) float hg[2][128];
    __shared__ __align__(16) float hd1[2][128];
    __shared__ __align__(16) float hd2[2][128];
    __shared__ __align__(16) float sred[8][4];   // per-warp {p0,pB,pC}
    __shared__ float zb[NSTEPS];

    const int b = blockIdx.x, tid = threadIdx.x;
    const int warp = tid >> 5, lane = tid & 31;

    for (int i = tid; i < NSTEPS; i += 256) zb[i] = g_zbar[b * NSTEPS + i];

    const int net = tid >> 7, j = tid & 127;
    const float* W1 = net ? si_W1 : mu_W1;
    const float* W2 = net ? si_W2 : mu_W2;
    const float w1a  = W1[j];
    const float w1b  = W1[128 + j];
    const float base = g_base[net][b][j];
    const float b2j  = (net ? si_b2 : mu_b2)[j];
    const float w3   = (net ? si_W3 : mu_W3)[j];
    const float b3m  = mu_b3[0], b3s = si_b3[0];
    const float du   = w1b * F_TSTEP;

    unsigned long long w2[64];
#pragma unroll
    for (int i = 0; i < 64; i++)
        w2[i] = pack2(W2[(2 * i) * 128 + j], W2[(2 * i + 1) * 128 + j]);

    float mean_r = r_ultimo[b];       // identical in every thread
    float asum = 0.0f;
    int s = 0;
    __syncthreads();                  // zb ready

    while (true) {
        // ---- exact refresh at step s (all warps) ----
        float v = fmaf(w1b, (float)s * F_TSTEP, fmaf(w1a, mean_r, base));
        float g1, g1p;
        gelu_vd(v, g1, g1p);
        hg[net][j]  = g1;
        hd1[net][j] = g1p * w1a;
        hd2[net][j] = g1p * du;
        __syncthreads();                              // (1)
        float A  = b2j + dot128(hg[net],  w2);
        float Bc = dot128(hd1[net], w2);
        float Cc = dot128(hd2[net], w2);
        float g2, g2p;
        gelu_vd(A, g2, g2p);
        float p0 = w3 * g2;
        float pB = w3 * g2p * Bc;
        float pC = w3 * g2p * Cc;
        p0 = wredsum(p0);
        pB = wredsum(pB);
        pC = wredsum(pC);
        if (lane == 0) {
            sred[warp][0] = p0; sred[warp][1] = pB; sred[warp][2] = pC;
        }
        __syncthreads();                              // (2)
        float mu0 = ((sred[0][0] + sred[1][0]) + (sred[2][0] + sred[3][0])) + b3m;
        float muB = ((sred[0][1] + sred[1][1]) + (sred[2][1] + sred[3][1]));
        float muC = ((sred[0][2] + sred[1][2]) + (sred[2][2] + sred[3][2]));
        float sp0 = ((sred[4][0] + sred[5][0]) + (sred[6][0] + sred[7][0])) + b3s;
        float spB = ((sred[4][1] + sred[5][1]) + (sred[6][1] + sred[7][1]));
        float spC = ((sred[4][2] + sred[5][2]) + (sred[6][2] + sred[7][2]));

        int e = s + WIN; if (e > NSTEPS) e = NSTEPS;
        const float mr = mean_r;
        float Dmr = 0.0f, fds = 0.0f;

        // ---- scalar window: no barriers, no reductions ----
        for (int ss = s; ss < e; ss++) {
            float zbs = zb[ss];
            float mu = fmaf(muB, Dmr, fmaf(muC, fds, mu0));
            float sp = fmaf(spB, Dmr, fmaf(spC, fds, sp0));
            float si = fmaxf(sp, 0.0f) +
                       __logf(1.0f + __expf(-fabsf(sp))) + 1e-5f;
            float dmr = fmaf(si, zbs, mu * F_DT);
            Dmr += dmr;
            fds += 1.0f;
            asum = fmaf(mr + Dmr, F_DT, asum);
        }
        mean_r = mr + Dmr;
        s = e;
        if (s >= NSTEPS) break;
        __syncthreads();                              // (3) sred/hg reuse
    }

    if (tid < 7) {
        float maxT = 0.0f;
#pragma unroll
        for (int m = 0; m < 7; m++) maxT = fmaxf(maxT, mat[m]);
        float frac = mat[tid] / (maxT + 1e-12f);
        out[b * 7 + tid] = (asum * frac) / (mat[tid] + 1e-12f);
    }
}

// ---------------------------------------------------------------------------
extern "C" void kernel_launch(void* const* d_in, const int* in_sizes, int n_in,
                              void* d_out, int out_size) {
    const float* X        = (const float*)d_in[0];
    const float* r_ultimo = (const float*)d_in[1];
    const float* mat      = (const float*)d_in[2];
    const float* Wp       = (const float*)d_in[3];
    const float* bp       = (const float*)d_in[4];
    const float* ln_g     = (const float*)d_in[5];
    const float* ln_b     = (const float*)d_in[6];
    const float* mu_W1    = (const float*)d_in[7];
    const float* mu_b1    = (const float*)d_in[8];
    const float* mu_W2    = (const float*)d_in[9];
    const float* mu_b2    = (const float*)d_in[10];
    const float* mu_W3    = (const float*)d_in[11];
    const float* mu_b3    = (const float*)d_in[12];
    const float* si_W1    = (const float*)d_in[13];
    const float* si_b1    = (const float*)d_in[14];
    const float* si_W2    = (const float*)d_in[15];
    const float* si_b2    = (const float*)d_in[16];
    const float* si_W3    = (const float*)d_in[17];
    const float* si_b3    = (const float*)d_in[18];
    float* out = (float*)d_out;

    keys_kernel<<<(NSTEPS + 255) / 256, 256>>>();
    dim3 zgrid(NSTEPS, BB);
    zbar_kernel<<<zgrid, 256>>>();
    prep_ctx_kernel<<<BB, TT>>>(X, Wp, bp, ln_g, ln_b,
                                mu_W1, mu_b1, si_W1, si_b1);
    sde_kernel<<<BB, 256>>>(r_ultimo, mat,
                            mu_W1, mu_W2, mu_b2, mu_W3, mu_b3,
                            si_W1, si_W2, si_b2, si_W3, si_b3,
                            out);
}

// round 16
// speedup vs baseline: 3.5388x; 1.9267x over previous
#include <cuda_runtime.h>
#include <stdint.h>

// ============================================================================
// ModeloNeuralVasicek — neural Vasicek SDE MC, exact-JAX-RNG, mean-collapsed,
// affine-windowed step map with refresh hidden behind the window.
// B=64, T=256, Q=256, n_steps=2520, WIN=60 (42 windows).
//
// Window w: scalar recurrence D <- (1+beta_s)*D + alpha_s (warp 0 only,
// 8-cycle chain), where alpha/beta come from a first-order model
//   mu ~ mu0 + muB*D + muC*ds,  si ~ si0 + siB*D + siC*ds  (softplus
// linearized at sp0).  Coefficients for window w+1 are computed by ALL warps
// DURING window w, linearized at an extrapolated mean m_hat (slope
// extrapolation) — a second-order-accurate choice, so the refresh leaves the
// serial critical path entirely.  Two barriers per window.
// ============================================================================

#define NSTEPS 2520
#define BB 64
#define TT 256
#define WIN 60
#define NWIN (NSTEPS / WIN)
#define F_DT 0.003968253968253968f
#define F_SQRT_DT 0.06299407883487119f
#define F_TSTEP (1.0f / 2519.0f)

__device__ float g_H[BB * TT * 64];
__device__ float g_base[2][BB][128];
__device__ float g_zbar[BB * NSTEPS];
__device__ unsigned int g_keys[NSTEPS * 2];

// ---------------------------------------------------------------------------
__device__ __forceinline__ void threefry2x32(uint32_t k0, uint32_t k1,
                                             uint32_t x0, uint32_t x1,
                                             uint32_t& o0, uint32_t& o1) {
    uint32_t ks2 = k0 ^ k1 ^ 0x1BD11BDAu;
    x0 += k0; x1 += k1;
#define TFR(r) { x0 += x1; x1 = __funnelshift_l(x1, x1, (r)); x1 ^= x0; }
    TFR(13) TFR(15) TFR(26) TFR(6)
    x0 += k1; x1 += ks2 + 1u;
    TFR(17) TFR(29) TFR(16) TFR(24)
    x0 += ks2; x1 += k0 + 2u;
    TFR(13) TFR(15) TFR(26) TFR(6)
    x0 += k0; x1 += k1 + 3u;
    TFR(17) TFR(29) TFR(16) TFR(24)
    x0 += k1; x1 += ks2 + 4u;
    TFR(13) TFR(15) TFR(26) TFR(6)
    x0 += ks2; x1 += k0 + 5u;
#undef TFR
    o0 = x0; o1 = x1;
}

// XLA ErfInv32 — log1p replaced by __logf(fmaf(-x,x,1)): same w to ~2 ulp.
__device__ __forceinline__ float erfinv_fast(float x) {
    float w = -__logf(fmaf(-x, x, 1.0f));
    float p;
    if (w < 5.0f) {
        w = w - 2.5f;
        p = 2.81022636e-08f;
        p = fmaf(p, w, 3.43273939e-07f);
        p = fmaf(p, w, -3.5233877e-06f);
        p = fmaf(p, w, -4.39150654e-06f);
        p = fmaf(p, w, 0.00021858087f);
        p = fmaf(p, w, -0.00125372503f);
        p = fmaf(p, w, -0.00417768164f);
        p = fmaf(p, w, 0.246640727f);
        p = fmaf(p, w, 1.50140941f);
    } else {
        w = sqrtf(w) - 3.0f;
        p = -0.000200214257f;
        p = fmaf(p, w, 0.000100950558f);
        p = fmaf(p, w, 0.00134934322f);
        p = fmaf(p, w, -0.00367342844f);
        p = fmaf(p, w, 0.00573950773f);
        p = fmaf(p, w, -0.0076224613f);
        p = fmaf(p, w, 0.00943887047f);
        p = fmaf(p, w, 1.00167406f);
        p = fmaf(p, w, 2.83297682f);
    }
    return p * x;
}

__device__ __forceinline__ void gelu_vd(float x, float& g, float& gp) {
    float e = erff(x * 0.70710678118654752f);
    float Phi = fmaf(0.5f, e, 0.5f);
    g = x * Phi;
    float phi = 0.3989422804014327f * __expf(-0.5f * x * x);
    gp = fmaf(x, phi, Phi);
}

__device__ __forceinline__ unsigned long long fma2(unsigned long long a,
                                                   unsigned long long b,
                                                   unsigned long long c) {
    unsigned long long d;
    asm("fma.rn.f32x2 %0, %1, %2, %3;" : "=l"(d) : "l"(a), "l"(b), "l"(c));
    return d;
}
__device__ __forceinline__ unsigned long long pack2(float lo, float hi) {
    unsigned long long v;
    asm("mov.b64 %0, {%1, %2};" : "=l"(v) : "f"(lo), "f"(hi));
    return v;
}
__device__ __forceinline__ float2 unpack2(unsigned long long v) {
    float2 r;
    asm("mov.b64 {%0, %1}, %2;" : "=f"(r.x), "=f"(r.y) : "l"(v));
    return r;
}

__device__ __forceinline__ float wredsum(float v) {
#pragma unroll
    for (int o = 16; o > 0; o >>= 1) v += __shfl_xor_sync(0xFFFFFFFFu, v, o);
    return v;
}

__device__ __forceinline__ float dot128(const float* hpf,
                                        const unsigned long long* w2) {
    const ulonglong2* hp = (const ulonglong2*)hpf;
    unsigned long long a0 = 0ull, a1 = 0ull, a2 = 0ull, a3 = 0ull;
    unsigned long long a4 = 0ull, a5 = 0ull, a6 = 0ull, a7 = 0ull;
#pragma unroll
    for (int i = 0; i < 8; i++) {
        ulonglong2 h01 = hp[4 * i + 0];
        ulonglong2 h23 = hp[4 * i + 1];
        ulonglong2 h45 = hp[4 * i + 2];
        ulonglong2 h67 = hp[4 * i + 3];
        a0 = fma2(h01.x, w2[8 * i + 0], a0);
        a1 = fma2(h01.y, w2[8 * i + 1], a1);
        a2 = fma2(h23.x, w2[8 * i + 2], a2);
        a3 = fma2(h23.y, w2[8 * i + 3], a3);
        a4 = fma2(h45.x, w2[8 * i + 4], a4);
        a5 = fma2(h45.y, w2[8 * i + 5], a5);
        a6 = fma2(h67.x, w2[8 * i + 6], a6);
        a7 = fma2(h67.y, w2[8 * i + 7], a7);
    }
    const unsigned long long one2 = 0x3F8000003F800000ull;
    a0 = fma2(a1, one2, a0);
    a2 = fma2(a3, one2, a2);
    a4 = fma2(a5, one2, a4);
    a6 = fma2(a7, one2, a6);
    float2 f0 = unpack2(a0), f2 = unpack2(a2), f4 = unpack2(a4), f6 = unpack2(a6);
    return ((f0.x + f0.y) + (f2.x + f2.y)) + ((f4.x + f4.y) + (f6.x + f6.y));
}

// ---------------------------------------------------------------------------
__global__ void keys_kernel() {
    int j = blockIdx.x * blockDim.x + threadIdx.x;
    if (j >= NSTEPS) return;
    uint32_t o0, o1;
    threefry2x32(0u, 1u, 0u, (uint32_t)j, o0, o1);
    g_keys[2 * j]     = o0;
    g_keys[2 * j + 1] = o1;
}

__global__ void zbar_kernel() {
    __shared__ float part[8];
    const int s = blockIdx.x, b = blockIdx.y, tid = threadIdx.x;
    const int warp = tid >> 5, lane = tid & 31;

    uint32_t k0 = __ldg(&g_keys[2 * s]);
    uint32_t k1 = __ldg(&g_keys[2 * s + 1]);
    uint32_t o0, o1;
    threefry2x32(k0, k1, 0u, (uint32_t)(b * 256 + tid), o0, o1);
    uint32_t bits = o0 ^ o1;

    float f = __uint_as_float((bits >> 9) | 0x3F800000u) - 1.0f;
    float u = fmaxf(fmaf(f, 2.0f, -0.99999994f), -0.99999994f);
    float z = 1.41421356237f * erfinv_fast(u);
    float dw = z * F_SQRT_DT;

    float sum = wredsum(dw);
    if (lane == 0) part[warp] = sum;
    __syncthreads();
    if (tid == 0) {
        float t = (((part[0] + part[1]) + (part[2] + part[3])) +
                   ((part[4] + part[5]) + (part[6] + part[7])));
        g_zbar[b * NSTEPS + s] = t * (1.0f / 256.0f);
    }
}

__global__ void prep_ctx_kernel(const float* __restrict__ X,
                                const float* __restrict__ Wp,
                                const float* __restrict__ bp,
                                const float* __restrict__ ln_g,
                                const float* __restrict__ ln_b,
                                const float* __restrict__ mu_W1,
                                const float* __restrict__ mu_b1,
                                const float* __restrict__ si_W1,
                                const float* __restrict__ si_b1) {
    __shared__ float ctx[192];
    const int b = blockIdx.x, tid = threadIdx.x;

    {
        const int t = tid;
        float x0 = X[(b * TT + t) * 2 + 0];
        float x1 = X[(b * TT + t) * 2 + 1];
        float h[64];
        float s = 0.0f;
#pragma unroll
        for (int j = 0; j < 64; j++) {
            float v = fmaf(x1, Wp[64 + j], fmaf(x0, Wp[j], bp[j]));
            h[j] = tanhf(v);
            s += h[j];
        }
        float m = s * (1.0f / 64.0f);
        float vv = 0.0f;
#pragma unroll
        for (int j = 0; j < 64; j++) { float d = h[j] - m; vv = fmaf(d, d, vv); }
        vv *= (1.0f / 64.0f);
        float den = sqrtf(vv + 1e-5f);
#pragma unroll
        for (int j = 0; j < 64; j++) {
            g_H[(b * TT + t) * 64 + j] = (h[j] - m) / den * ln_g[j] + ln_b[j];
        }
    }
    __syncthreads();

    if (tid < 64) {
        int j = tid;
        const float* Hb = g_H + b * TT * 64;
        float s = 0.0f;
        for (int t = 0; t < TT; t++) s += Hb[t * 64 + j];
        float mean = s * (1.0f / 256.0f);
        float ss = 0.0f;
        for (int t = 0; t < TT; t++) { float d = Hb[t * 64 + j] - mean; ss = fmaf(d, d, ss); }
        float sd = sqrtf(ss * (1.0f / 255.0f));
        ctx[j]       = mean;
        ctx[64 + j]  = sd;
        ctx[128 + j] = Hb[255 * 64 + j];
    }
    __syncthreads();
    int net = tid >> 7, j = tid & 127;
    const float* W1 = net ? si_W1 : mu_W1;
    float acc = (net ? si_b1 : mu_b1)[j];
    for (int i = 0; i < 192; i++)
        acc = fmaf(ctx[i], W1[(2 + i) * 128 + j], acc);
    g_base[net][b][j] = acc;
}

// ---------------------------------------------------------------------------
// SDE kernel.
// ---------------------------------------------------------------------------
__global__ void __launch_bounds__(256, 1) sde_kernel(
    const float* __restrict__ r_ultimo, const float* __restrict__ mat,
    const float* __restrict__ mu_W1, const float* __restrict__ mu_W2,
    const float* __restrict__ mu_b2, const float* __restrict__ mu_W3,
    const float* __restrict__ mu_b3,
    const float* __restrict__ si_W1, const float* __restrict__ si_W2,
    const float* __restrict__ si_b2, const float* __restrict__ si_W3,
    const float* __restrict__ si_b3,
    float* __restrict__ out) {

    __shared__ __align__(16) float hg[2][128];
    __shared__ __align__(16) float hd1[2][128];
    __shared__ __align__(16) float hd2[2][128];
    __shared__ __align__(16) float sred[8][4];   // per-warp {p0,pB,pC}
    __shared__ float sc_Dend;
    __shared__ float zb[NSTEPS];

    const int b = blockIdx.x, tid = threadIdx.x;
    const int warp = tid >> 5, lane = tid & 31;

    for (int i = tid; i < NSTEPS; i += 256) zb[i] = g_zbar[b * NSTEPS + i];

    const int net = tid >> 7, j = tid & 127;
    const float* W1 = net ? si_W1 : mu_W1;
    const float* W2 = net ? si_W2 : mu_W2;
    const float w1a  = W1[j];
    const float w1b  = W1[128 + j];
    const float base = g_base[net][b][j];
    const float b2j  = (net ? si_b2 : mu_b2)[j];
    const float w3   = (net ? si_W3 : mu_W3)[j];
    const float b3m  = mu_b3[0], b3s = si_b3[0];
    const float du   = w1b * F_TSTEP;

    unsigned long long w2[64];
#pragma unroll
    for (int i = 0; i < 64; i++)
        w2[i] = pack2(W2[(2 * i) * 128 + j], W2[(2 * i + 1) * 128 + j]);

    const float mr0 = r_ultimo[b];
    float asum = 0.0f;                 // meaningful in warp 0

    // refresh-coefficient registers (scalar model of the step map)
    float aM, bM, cM, si0, siB, siC;

    // ---- prologue: K_0 at (mr0, t=0) ----
    {
        float v0 = fmaf(w1a, mr0, base);
        float g1, g1p;
        gelu_vd(v0, g1, g1p);
        hg[net][j]  = g1;
        hd1[net][j] = g1p * w1a;
        hd2[net][j] = g1p * du;
        __syncthreads();
        float A  = b2j + dot128(hg[net],  w2);
        float Bc = dot128(hd1[net], w2);
        float Cc = dot128(hd2[net], w2);
        float g2, g2p;
        gelu_vd(A, g2, g2p);
        float p0 = wredsum(w3 * g2);
        float pB = wredsum(w3 * g2p * Bc);
        float pC = wredsum(w3 * g2p * Cc);
        if (lane == 0) { sred[warp][0] = p0; sred[warp][1] = pB; sred[warp][2] = pC; }
        __syncthreads();
        float mu0 = ((sred[0][0] + sred[1][0]) + (sred[2][0] + sred[3][0])) + b3m;
        float muB = ((sred[0][1] + sred[1][1]) + (sred[2][1] + sred[3][1]));
        float muC = ((sred[0][2] + sred[1][2]) + (sred[2][2] + sred[3][2]));
        float sp0 = ((sred[4][0] + sred[5][0]) + (sred[6][0] + sred[7][0])) + b3s;
        float spB = ((sred[4][1] + sred[5][1]) + (sred[6][1] + sred[7][1]));
        float spC = ((sred[4][2] + sred[5][2]) + (sred[6][2] + sred[7][2]));
        aM = mu0 * F_DT; bM = muB * F_DT; cM = muC * F_DT;
        float ef = __expf(-fabsf(sp0));
        float den = 1.0f + ef;
        si0 = fmaxf(sp0, 0.0f) + __logf(den) + 1e-5f;
        float sig = (sp0 >= 0.0f) ? (1.0f / den) : (ef / den);
        siB = sig * spB; siC = sig * spC;
    }

    float mhat_prev = mr0, mhat_cur = mr0, mstart_prev = mr0;

    for (int w = 0; w < NWIN; w++) {
        const int s = w * WIN;
        float m_start = (w == 0) ? mr0 : (mhat_prev + sc_Dend);
        float slope   = m_start - mstart_prev;
        float mhat_next = m_start + slope;      // extrapolated lin point (2nd-order ok)

        // --- prepare K_{w+1} inputs at (mhat_next, t_{s+WIN}) ---
        float vh = fmaf(w1b, (float)(s + WIN) * F_TSTEP, fmaf(w1a, mhat_next, base));
        float g1, g1p;
        gelu_vd(vh, g1, g1p);
        hg[net][j]  = g1;
        hd1[net][j] = g1p * w1a;
        hd2[net][j] = g1p * du;
        __syncthreads();                              // bar 1

        // --- dots for K_{w+1} (all warps) ---
        float A  = b2j + dot128(hg[net],  w2);
        float Bc = dot128(hd1[net], w2);
        float Cc = dot128(hd2[net], w2);
        float g2, g2p;
        gelu_vd(A, g2, g2p);
        float p0 = wredsum(w3 * g2);
        float pB = wredsum(w3 * g2p * Bc);
        float pC = wredsum(w3 * g2p * Cc);
        if (lane == 0) { sred[warp][0] = p0; sred[warp][1] = pB; sred[warp][2] = pC; }

        // --- warp 0: affine scalar window w (uses K_w) ---
        if (warp == 0) {
            float D = m_start - mhat_cur;
            float S = 0.0f;
            const float* zp = zb + s;
#pragma unroll 15
            for (int k = 0; k < WIN; k++) {
                float zbk = zp[k];
                float t3 = fmaf(cM, (float)k, aM);
                float t2 = fmaf(siC, (float)k, si0);
                float alpha = fmaf(t2, zbk, t3);
                float beta  = fmaf(siB, zbk, bM);
                float tD = D + alpha;
                D = fmaf(beta, D, tD);
                S += D;
            }
            if (lane == 0) sc_Dend = D;
            asum = fmaf(fmaf((float)WIN, mhat_cur, S), F_DT, asum);
        }
        __syncthreads();                              // bar 2

        // --- finalize K_{w+1} (all threads; cheap) ---
        float mu0 = ((sred[0][0] + sred[1][0]) + (sred[2][0] + sred[3][0])) + b3m;
        float muB = ((sred[0][1] + sred[1][1]) + (sred[2][1] + sred[3][1]));
        float muC = ((sred[0][2] + sred[1][2]) + (sred[2][2] + sred[3][2]));
        float sp0 = ((sred[4][0] + sred[5][0]) + (sred[6][0] + sred[7][0])) + b3s;
        float spB = ((sred[4][1] + sred[5][1]) + (sred[6][1] + sred[7][1]));
        float spC = ((sred[4][2] + sred[5][2]) + (sred[6][2] + sred[7][2]));
        aM = mu0 * F_DT; bM = muB * F_DT; cM = muC * F_DT;
        float ef = __expf(-fabsf(sp0));
        float den = 1.0f + ef;
        si0 = fmaxf(sp0, 0.0f) + __logf(den) + 1e-5f;
        float sig = (sp0 >= 0.0f) ? (1.0f / den) : (ef / den);
        siB = sig * spB; siC = sig * spC;

        mhat_prev = mhat_cur;
        mstart_prev = m_start;
        mhat_cur = mhat_next;
    }

    if (tid < 7) {                                    // warp 0 holds asum
        float maxT = 0.0f;
#pragma unroll
        for (int m = 0; m < 7; m++) maxT = fmaxf(maxT, mat[m]);
        float frac = mat[tid] / (maxT + 1e-12f);
        out[b * 7 + tid] = (asum * frac) / (mat[tid] + 1e-12f);
    }
}

// ---------------------------------------------------------------------------
extern "C" void kernel_launch(void* const* d_in, const int* in_sizes, int n_in,
                              void* d_out, int out_size) {
    const float* X        = (const float*)d_in[0];
    const float* r_ultimo = (const float*)d_in[1];
    const float* mat      = (const float*)d_in[2];
    const float* Wp       = (const float*)d_in[3];
    const float* bp       = (const float*)d_in[4];
    const float* ln_g     = (const float*)d_in[5];
    const float* ln_b     = (const float*)d_in[6];
    const float* mu_W1    = (const float*)d_in[7];
    const float* mu_b1    = (const float*)d_in[8];
    const float* mu_W2    = (const float*)d_in[9];
    const float* mu_b2    = (const float*)d_in[10];
    const float* mu_W3    = (const float*)d_in[11];
    const float* mu_b3    = (const float*)d_in[12];
    const float* si_W1    = (const float*)d_in[13];
    const float* si_b1    = (const float*)d_in[14];
    const float* si_W2    = (const float*)d_in[15];
    const float* si_b2    = (const float*)d_in[16];
    const float* si_W3    = (const float*)d_in[17];
    const float* si_b3    = (const float*)d_in[18];
    float* out = (float*)d_out;

    keys_kernel<<<(NSTEPS + 255) / 256, 256>>>();
    dim3 zgrid(NSTEPS, BB);
    zbar_kernel<<<zgrid, 256>>>();
    prep_ctx_kernel<<<BB, TT>>>(X, Wp, bp, ln_g, ln_b,
                                mu_W1, mu_b1, si_W1, si_b1);
    sde_kernel<<<BB, 256>>>(r_ultimo, mat,
                            mu_W1, mu_W2, mu_b2, mu_W3, mu_b3,
                            si_W1, si_W2, si_b2, si_W3, si_b3,
                            out);
}

// round 17
// speedup vs baseline: 4.7239x; 1.3349x over previous
#include <cuda_runtime.h>
#include <stdint.h>

// ============================================================================
// ModeloNeuralVasicek — neural Vasicek SDE MC, exact-JAX-RNG, mean-collapsed,
// affine-windowed step map (WIN=120) + warp-per-cell zbar (8 normals/lane).
// B=64, T=256, Q=256, n_steps=2520.
// ============================================================================

#define NSTEPS 2520
#define BB 64
#define TT 256
#define WIN 120
#define NWIN (NSTEPS / WIN)
#define F_DT 0.003968253968253968f
#define F_SQRT_DT 0.06299407883487119f
#define F_TSTEP (1.0f / 2519.0f)

__device__ float g_H[BB * TT * 64];
__device__ float g_base[2][BB][128];
__device__ float g_zbar[BB * NSTEPS];
__device__ unsigned int g_keys[NSTEPS * 2];

// ---------------------------------------------------------------------------
__device__ __forceinline__ void threefry2x32(uint32_t k0, uint32_t k1,
                                             uint32_t x0, uint32_t x1,
                                             uint32_t& o0, uint32_t& o1) {
    uint32_t ks2 = k0 ^ k1 ^ 0x1BD11BDAu;
    x0 += k0; x1 += k1;
#define TFR(r) { x0 += x1; x1 = __funnelshift_l(x1, x1, (r)); x1 ^= x0; }
    TFR(13) TFR(15) TFR(26) TFR(6)
    x0 += k1; x1 += ks2 + 1u;
    TFR(17) TFR(29) TFR(16) TFR(24)
    x0 += ks2; x1 += k0 + 2u;
    TFR(13) TFR(15) TFR(26) TFR(6)
    x0 += k0; x1 += k1 + 3u;
    TFR(17) TFR(29) TFR(16) TFR(24)
    x0 += k1; x1 += ks2 + 4u;
    TFR(13) TFR(15) TFR(26) TFR(6)
    x0 += ks2; x1 += k0 + 5u;
#undef TFR
    o0 = x0; o1 = x1;
}

// XLA ErfInv32 — log1p via __logf(fmaf(-x,x,1)): same w to ~2 ulp.
__device__ __forceinline__ float erfinv_fast(float x) {
    float w = -__logf(fmaf(-x, x, 1.0f));
    float p;
    if (w < 5.0f) {
        w = w - 2.5f;
        p = 2.81022636e-08f;
        p = fmaf(p, w, 3.43273939e-07f);
        p = fmaf(p, w, -3.5233877e-06f);
        p = fmaf(p, w, -4.39150654e-06f);
        p = fmaf(p, w, 0.00021858087f);
        p = fmaf(p, w, -0.00125372503f);
        p = fmaf(p, w, -0.00417768164f);
        p = fmaf(p, w, 0.246640727f);
        p = fmaf(p, w, 1.50140941f);
    } else {
        w = sqrtf(w) - 3.0f;
        p = -0.000200214257f;
        p = fmaf(p, w, 0.000100950558f);
        p = fmaf(p, w, 0.00134934322f);
        p = fmaf(p, w, -0.00367342844f);
        p = fmaf(p, w, 0.00573950773f);
        p = fmaf(p, w, -0.0076224613f);
        p = fmaf(p, w, 0.00943887047f);
        p = fmaf(p, w, 1.00167406f);
        p = fmaf(p, w, 2.83297682f);
    }
    return p * x;
}

__device__ __forceinline__ void gelu_vd(float x, float& g, float& gp) {
    float e = erff(x * 0.70710678118654752f);
    float Phi = fmaf(0.5f, e, 0.5f);
    g = x * Phi;
    float phi = 0.3989422804014327f * __expf(-0.5f * x * x);
    gp = fmaf(x, phi, Phi);
}

__device__ __forceinline__ unsigned long long fma2(unsigned long long a,
                                                   unsigned long long b,
                                                   unsigned long long c) {
    unsigned long long d;
    asm("fma.rn.f32x2 %0, %1, %2, %3;" : "=l"(d) : "l"(a), "l"(b), "l"(c));
    return d;
}
__device__ __forceinline__ unsigned long long pack2(float lo, float hi) {
    unsigned long long v;
    asm("mov.b64 %0, {%1, %2};" : "=l"(v) : "f"(lo), "f"(hi));
    return v;
}
__device__ __forceinline__ float2 unpack2(unsigned long long v) {
    float2 r;
    asm("mov.b64 {%0, %1}, %2;" : "=f"(r.x), "=f"(r.y) : "l"(v));
    return r;
}

__device__ __forceinline__ float wredsum(float v) {
#pragma unroll
    for (int o = 16; o > 0; o >>= 1) v += __shfl_xor_sync(0xFFFFFFFFu, v, o);
    return v;
}

__device__ __forceinline__ float dot128(const float* hpf,
                                        const unsigned long long* w2) {
    const ulonglong2* hp = (const ulonglong2*)hpf;
    unsigned long long a0 = 0ull, a1 = 0ull, a2 = 0ull, a3 = 0ull;
    unsigned long long a4 = 0ull, a5 = 0ull, a6 = 0ull, a7 = 0ull;
#pragma unroll
    for (int i = 0; i < 8; i++) {
        ulonglong2 h01 = hp[4 * i + 0];
        ulonglong2 h23 = hp[4 * i + 1];
        ulonglong2 h45 = hp[4 * i + 2];
        ulonglong2 h67 = hp[4 * i + 3];
        a0 = fma2(h01.x, w2[8 * i + 0], a0);
        a1 = fma2(h01.y, w2[8 * i + 1], a1);
        a2 = fma2(h23.x, w2[8 * i + 2], a2);
        a3 = fma2(h23.y, w2[8 * i + 3], a3);
        a4 = fma2(h45.x, w2[8 * i + 4], a4);
        a5 = fma2(h45.y, w2[8 * i + 5], a5);
        a6 = fma2(h67.x, w2[8 * i + 6], a6);
        a7 = fma2(h67.y, w2[8 * i + 7], a7);
    }
    const unsigned long long one2 = 0x3F8000003F800000ull;
    a0 = fma2(a1, one2, a0);
    a2 = fma2(a3, one2, a2);
    a4 = fma2(a5, one2, a4);
    a6 = fma2(a7, one2, a6);
    float2 f0 = unpack2(a0), f2 = unpack2(a2), f4 = unpack2(a4), f6 = unpack2(a6);
    return ((f0.x + f0.y) + (f2.x + f2.y)) + ((f4.x + f4.y) + (f6.x + f6.y));
}

// ---------------------------------------------------------------------------
__global__ void keys_kernel() {
    int j = blockIdx.x * blockDim.x + threadIdx.x;
    if (j >= NSTEPS) return;
    uint32_t o0, o1;
    threefry2x32(0u, 1u, 0u, (uint32_t)j, o0, o1);
    g_keys[2 * j]     = o0;
    g_keys[2 * j + 1] = o1;
}

// ---------------------------------------------------------------------------
// zbar: one warp per (b,s) cell; 8 normals per lane (independent chains);
// no __syncthreads.  Grid = 161280/8 blocks of 256 threads.
// ---------------------------------------------------------------------------
__global__ void __launch_bounds__(256) zbar_kernel() {
    const int warp = threadIdx.x >> 5, lane = threadIdx.x & 31;
    const int cell = blockIdx.x * 8 + warp;       // cell = s*64 + b
    const int s = cell >> 6, b = cell & 63;

    const uint32_t k0 = __ldg(&g_keys[2 * s]);
    const uint32_t k1 = __ldg(&g_keys[2 * s + 1]);
    const uint32_t cbase = (uint32_t)(b * 256 + lane);

    float acc = 0.0f;
#pragma unroll
    for (int k = 0; k < 8; k++) {
        uint32_t o0, o1;
        threefry2x32(k0, k1, 0u, cbase + 32u * k, o0, o1);
        uint32_t bits = o0 ^ o1;
        float f = __uint_as_float((bits >> 9) | 0x3F800000u) - 1.0f;
        float u = fmaxf(fmaf(f, 2.0f, -0.99999994f), -0.99999994f);
        acc += erfinv_fast(u);
    }
    float sum = wredsum(acc);
    if (lane == 0)
        g_zbar[b * NSTEPS + s] = sum * (1.41421356237f * F_SQRT_DT / 256.0f);
}

// ---------------------------------------------------------------------------
__global__ void prep_ctx_kernel(const float* __restrict__ X,
                                const float* __restrict__ Wp,
                                const float* __restrict__ bp,
                                const float* __restrict__ ln_g,
                                const float* __restrict__ ln_b,
                                const float* __restrict__ mu_W1,
                                const float* __restrict__ mu_b1,
                                const float* __restrict__ si_W1,
                                const float* __restrict__ si_b1) {
    __shared__ float ctx[192];
    __shared__ float part[4][64];
    const int b = blockIdx.x, tid = threadIdx.x;

    {   // phase 1: H = LN(tanh(X@Wp+bp)), one thread per t
        const int t = tid;
        float x0 = X[(b * TT + t) * 2 + 0];
        float x1 = X[(b * TT + t) * 2 + 1];
        float h[64];
        float s = 0.0f;
#pragma unroll
        for (int j = 0; j < 64; j++) {
            float v = fmaf(x1, Wp[64 + j], fmaf(x0, Wp[j], bp[j]));
            h[j] = tanhf(v);
            s += h[j];
        }
        float m = s * (1.0f / 64.0f);
        float vv = 0.0f;
#pragma unroll
        for (int j = 0; j < 64; j++) { float d = h[j] - m; vv = fmaf(d, d, vv); }
        vv *= (1.0f / 64.0f);
        float den = sqrtf(vv + 1e-5f);
#pragma unroll
        for (int j = 0; j < 64; j++) {
            g_H[(b * TT + t) * 64 + j] = (h[j] - m) / den * ln_g[j] + ln_b[j];
        }
    }
    __syncthreads();

    // phase 2: ctx mean/std over T, 4-way parallel partials
    const int jj = tid & 63, q = tid >> 6;
    const float* Hbj = g_H + b * TT * 64 + jj;
    {
        float s1 = 0.0f;
        for (int t = q * 64; t < q * 64 + 64; t++) s1 += Hbj[t * 64];
        part[q][jj] = s1;
    }
    __syncthreads();
    float mean_j = ((part[0][jj] + part[1][jj]) +
                    (part[2][jj] + part[3][jj])) * (1.0f / 256.0f);
    __syncthreads();
    {
        float s2 = 0.0f;
        for (int t = q * 64; t < q * 64 + 64; t++) {
            float d = Hbj[t * 64] - mean_j;
            s2 = fmaf(d, d, s2);
        }
        part[q][jj] = s2;
    }
    __syncthreads();
    if (tid < 64) {
        float ss = ((part[0][tid] + part[1][tid]) +
                    (part[2][tid] + part[3][tid]));
        ctx[tid]       = mean_j;                       // jj == tid here
        ctx[64 + tid]  = sqrtf(ss * (1.0f / 255.0f));  // ddof=1
        ctx[128 + tid] = g_H[b * TT * 64 + 255 * 64 + tid];
    }
    __syncthreads();

    int net = tid >> 7, j = tid & 127;
    const float* W1 = net ? si_W1 : mu_W1;
    float acc = (net ? si_b1 : mu_b1)[j];
    for (int i = 0; i < 192; i++)
        acc = fmaf(ctx[i], W1[(2 + i) * 128 + j], acc);
    g_base[net][b][j] = acc;
}

// ---------------------------------------------------------------------------
// SDE kernel: affine windows, refresh for K_{w+1} computed concurrently with
// window w's scalar loop (linearized at an extrapolated mean — 2nd-order ok).
// ---------------------------------------------------------------------------
__global__ void __launch_bounds__(256, 1) sde_kernel(
    const float* __restrict__ r_ultimo, const float* __restrict__ mat,
    const float* __restrict__ mu_W1, const float* __restrict__ mu_W2,
    const float* __restrict__ mu_b2, const float* __restrict__ mu_W3,
    const float* __restrict__ mu_b3,
    const float* __restrict__ si_W1, const float* __restrict__ si_W2,
    const float* __restrict__ si_b2, const float* __restrict__ si_W3,
    const float* __restrict__ si_b3,
    float* __restrict__ out) {

    __shared__ __align__(16) float hg[2][128];
    __shared__ __align__(16) float hd1[2][128];
    __shared__ __align__(16) float hd2[2][128];
    __shared__ __align__(16) float sred[8][4];
    __shared__ float sc_Dend;
    __shared__ float zb[NSTEPS];

    const int b = blockIdx.x, tid = threadIdx.x;
    const int warp = tid >> 5, lane = tid & 31;

    for (int i = tid; i < NSTEPS; i += 256) zb[i] = g_zbar[b * NSTEPS + i];

    const int net = tid >> 7, j = tid & 127;
    const float* W1 = net ? si_W1 : mu_W1;
    const float* W2 = net ? si_W2 : mu_W2;
    const float w1a  = W1[j];
    const float w1b  = W1[128 + j];
    const float base = g_base[net][b][j];
    const float b2j  = (net ? si_b2 : mu_b2)[j];
    const float w3   = (net ? si_W3 : mu_W3)[j];
    const float b3m  = mu_b3[0], b3s = si_b3[0];
    const float du   = w1b * F_TSTEP;

    unsigned long long w2[64];
#pragma unroll
    for (int i = 0; i < 64; i++)
        w2[i] = pack2(W2[(2 * i) * 128 + j], W2[(2 * i + 1) * 128 + j]);

    const float mr0 = r_ultimo[b];
    float asum = 0.0f;

    float aM, bM, cM, si0, siB, siC;

    // ---- prologue: K_0 at (mr0, t=0) ----
    {
        float v0 = fmaf(w1a, mr0, base);
        float g1, g1p;
        gelu_vd(v0, g1, g1p);
        hg[net][j]  = g1;
        hd1[net][j] = g1p * w1a;
        hd2[net][j] = g1p * du;
        __syncthreads();
        float A  = b2j + dot128(hg[net],  w2);
        float Bc = dot128(hd1[net], w2);
        float Cc = dot128(hd2[net], w2);
        float g2, g2p;
        gelu_vd(A, g2, g2p);
        float p0 = wredsum(w3 * g2);
        float pB = wredsum(w3 * g2p * Bc);
        float pC = wredsum(w3 * g2p * Cc);
        if (lane == 0) { sred[warp][0] = p0; sred[warp][1] = pB; sred[warp][2] = pC; }
        __syncthreads();
        float mu0 = ((sred[0][0] + sred[1][0]) + (sred[2][0] + sred[3][0])) + b3m;
        float muB = ((sred[0][1] + sred[1][1]) + (sred[2][1] + sred[3][1]));
        float muC = ((sred[0][2] + sred[1][2]) + (sred[2][2] + sred[3][2]));
        float sp0 = ((sred[4][0] + sred[5][0]) + (sred[6][0] + sred[7][0])) + b3s;
        float spB = ((sred[4][1] + sred[5][1]) + (sred[6][1] + sred[7][1]));
        float spC = ((sred[4][2] + sred[5][2]) + (sred[6][2] + sred[7][2]));
        aM = mu0 * F_DT; bM = muB * F_DT; cM = muC * F_DT;
        float ef = __expf(-fabsf(sp0));
        float den = 1.0f + ef;
        si0 = fmaxf(sp0, 0.0f) + __logf(den) + 1e-5f;
        float sig = (sp0 >= 0.0f) ? (1.0f / den) : (ef / den);
        siB = sig * spB; siC = sig * spC;
    }

    float mhat_prev = mr0, mhat_cur = mr0, mstart_prev = mr0;

    for (int w = 0; w < NWIN; w++) {
        const int s = w * WIN;
        float m_start = (w == 0) ? mr0 : (mhat_prev + sc_Dend);
        float slope   = m_start - mstart_prev;
        float mhat_next = m_start + slope;

        // --- K_{w+1} inputs at (mhat_next, t_{s+WIN}) ---
        float vh = fmaf(w1b, (float)(s + WIN) * F_TSTEP, fmaf(w1a, mhat_next, base));
        float g1, g1p;
        gelu_vd(vh, g1, g1p);
        hg[net][j]  = g1;
        hd1[net][j] = g1p * w1a;
        hd2[net][j] = g1p * du;
        __syncthreads();                              // bar 1

        // --- dots for K_{w+1} (all warps, concurrent with warp-0 window) ---
        float A  = b2j + dot128(hg[net],  w2);
        float Bc = dot128(hd1[net], w2);
        float Cc = dot128(hd2[net], w2);
        float g2, g2p;
        gelu_vd(A, g2, g2p);
        float p0 = wredsum(w3 * g2);
        float pB = wredsum(w3 * g2p * Bc);
        float pC = wredsum(w3 * g2p * Cc);
        if (lane == 0) { sred[warp][0] = p0; sred[warp][1] = pB; sred[warp][2] = pC; }

        // --- warp 0: affine scalar window w (uses K_w) ---
        if (warp == 0) {
            float D = m_start - mhat_cur;
            float S = 0.0f;
            const float* zp = zb + s;
#pragma unroll 15
            for (int k = 0; k < WIN; k++) {
                float zbk = zp[k];
                float t3 = fmaf(cM, (float)k, aM);
                float t2 = fmaf(siC, (float)k, si0);
                float alpha = fmaf(t2, zbk, t3);
                float beta  = fmaf(siB, zbk, bM);
                float tD = D + alpha;
                D = fmaf(beta, D, tD);
                S += D;
            }
            if (lane == 0) sc_Dend = D;
            asum = fmaf(fmaf((float)WIN, mhat_cur, S), F_DT, asum);
        }
        __syncthreads();                              // bar 2

        // --- finalize K_{w+1} ---
        float mu0 = ((sred[0][0] + sred[1][0]) + (sred[2][0] + sred[3][0])) + b3m;
        float muB = ((sred[0][1] + sred[1][1]) + (sred[2][1] + sred[3][1]));
        float muC = ((sred[0][2] + sred[1][2]) + (sred[2][2] + sred[3][2]));
        float sp0 = ((sred[4][0] + sred[5][0]) + (sred[6][0] + sred[7][0])) + b3s;
        float spB = ((sred[4][1] + sred[5][1]) + (sred[6][1] + sred[7][1]));
        float spC = ((sred[4][2] + sred[5][2]) + (sred[6][2] + sred[7][2]));
        aM = mu0 * F_DT; bM = muB * F_DT; cM = muC * F_DT;
        float ef = __expf(-fabsf(sp0));
        float den = 1.0f + ef;
        si0 = fmaxf(sp0, 0.0f) + __logf(den) + 1e-5f;
        float sig = (sp0 >= 0.0f) ? (1.0f / den) : (ef / den);
        siB = sig * spB; siC = sig * spC;

        mhat_prev = mhat_cur;
        mstart_prev = m_start;
        mhat_cur = mhat_next;
    }

    if (tid < 7) {
        float maxT = 0.0f;
#pragma unroll
        for (int m = 0; m < 7; m++) maxT = fmaxf(maxT, mat[m]);
        float frac = mat[tid] / (maxT + 1e-12f);
        out[b * 7 + tid] = (asum * frac) / (mat[tid] + 1e-12f);
    }
}

// ---------------------------------------------------------------------------
extern "C" void kernel_launch(void* const* d_in, const int* in_sizes, int n_in,
                              void* d_out, int out_size) {
    const float* X        = (const float*)d_in[0];
    const float* r_ultimo = (const float*)d_in[1];
    const float* mat      = (const float*)d_in[2];
    const float* Wp       = (const float*)d_in[3];
    const float* bp       = (const float*)d_in[4];
    const float* ln_g     = (const float*)d_in[5];
    const float* ln_b     = (const float*)d_in[6];
    const float* mu_W1    = (const float*)d_in[7];
    const float* mu_b1    = (const float*)d_in[8];
    const float* mu_W2    = (const float*)d_in[9];
    const float* mu_b2    = (const float*)d_in[10];
    const float* mu_W3    = (const float*)d_in[11];
    const float* mu_b3    = (const float*)d_in[12];
    const float* si_W1    = (const float*)d_in[13];
    const float* si_b1    = (const float*)d_in[14];
    const float* si_W2    = (const float*)d_in[15];
    const float* si_b2    = (const float*)d_in[16];
    const float* si_W3    = (const float*)d_in[17];
    const float* si_b3    = (const float*)d_in[18];
    float* out = (float*)d_out;

    keys_kernel<<<(NSTEPS + 255) / 256, 256>>>();
    zbar_kernel<<<(NSTEPS * BB) / 8, 256>>>();
    prep_ctx_kernel<<<BB, TT>>>(X, Wp, bp, ln_g, ln_b,
                                mu_W1, mu_b1, si_W1, si_b1);
    sde_kernel<<<BB, 256>>>(r_ultimo, mat,
                            mu_W1, mu_W2, mu_b2, mu_W3, mu_b3,
                            si_W1, si_W2, si_b2, si_W3, si_b3,
                            out);
}